// round 2
// baseline (speedup 1.0000x reference)
#include <cuda_runtime.h>
#include <cstdint>

#define DT_C    0.054f
#define GAMMA_C 4.9f
#define EPS_C   4.8f

constexpr int Bn = 64, Tn = 1024, In = 256, Hn = 512;
constexpr int WROW = In + 2 * Hn;     // 1280 floats per W row
constexpr int KS   = 2 * Hn;          // 1024 state dim [hz|hy]
constexpr int NG   = 8;               // batch groups
constexpr int GC   = 16;              // CTAs per group (each owns 32 h)
constexpr int PS   = 1028;            // smem row pitch (floats), conflict-free
constexpr int PS4  = PS / 4;          // 257 float4

// Scratch (allowed: __device__ globals). Double-buffered state + group barriers.
__device__ float g_state[2][Bn][KS];
__device__ unsigned int g_bar[NG];

// ---------------------------------------------------------------------------
// init: zero state buffer 0 and barrier counters (every launch, for graph replay)
// ---------------------------------------------------------------------------
__global__ void cornn_init_kernel() {
    int i = blockIdx.x * blockDim.x + threadIdx.x;
    float* s0 = &g_state[0][0][0];
    if (i < Bn * KS) s0[i] = 0.0f;
    if (i < NG) g_bar[i] = 0u;
}

// ---------------------------------------------------------------------------
// GEMM: out[m, h] = sum_i X[m, i] * W[h, i] + bias[h]
//   X is (B*T, 256) row-major; W rows have stride 1280 (first 256 cols = Wx)
//   out is (B*T, 512) row-major == (B, T, H)
// Tiles: 128m x 64n x 16k, double-buffered.
// ---------------------------------------------------------------------------
__global__ void __launch_bounds__(256) cornn_gemm_kernel(
    const float* __restrict__ X, const float* __restrict__ Wg,
    const float* __restrict__ bias, float* __restrict__ out)
{
    constexpr int BM = 128, BN = 64, BK = 16, NCH = In / BK; // 16 chunks
    __shared__ float As[2][BK][BM + 4];   // [k][m], pitch 132
    __shared__ float Bs[2][BK][BN + 4];   // [k][n], pitch 68

    const int tid = threadIdx.x;
    const int m0 = blockIdx.x * BM;
    const int n0 = blockIdx.y * BN;
    const int tx = tid & 15;   // n: 4 cols each
    const int ty = tid >> 4;   // m: 8 rows each

    // A-chunk: 512 float4 (128 rows x 4 f4). q = tid, tid+256.
    const int rowA0 = tid >> 2,           kqA0 = tid & 3;
    const int rowA1 = (tid + 256) >> 2,   kqA1 = tid & 3;       // (tid+256)&3 == tid&3
    // B-chunk: 256 float4 (64 rows x 4 f4). q = tid.
    const int rowB = tid >> 2, kqB = tid & 3;

    const float4* X4 = (const float4*)X;
    const float4* W4 = (const float4*)Wg;

    float acc[8][4];
#pragma unroll
    for (int i = 0; i < 8; i++)
#pragma unroll
        for (int j = 0; j < 4; j++) acc[i][j] = 0.0f;

    // prologue: chunk 0
    float4 a0 = X4[(size_t)(m0 + rowA0) * 64 + kqA0];
    float4 a1 = X4[(size_t)(m0 + rowA1) * 64 + kqA1];
    float4 bb = W4[(size_t)(n0 + rowB) * 320 + kqB];
    {
#pragma unroll
        for (int c = 0; c < 4; c++) {
            As[0][kqA0 * 4 + c][rowA0] = ((const float*)&a0)[c];
            As[0][kqA1 * 4 + c][rowA1] = ((const float*)&a1)[c];
            Bs[0][kqB * 4 + c][rowB]   = ((const float*)&bb)[c];
        }
    }
    __syncthreads();

    for (int kc = 0; kc < NCH; ++kc) {
        const int cur = kc & 1;
        float4 nA0, nA1, nB;
        if (kc + 1 < NCH) {
            nA0 = X4[(size_t)(m0 + rowA0) * 64 + (kc + 1) * 4 + kqA0];
            nA1 = X4[(size_t)(m0 + rowA1) * 64 + (kc + 1) * 4 + kqA1];
            nB  = W4[(size_t)(n0 + rowB) * 320 + (kc + 1) * 4 + kqB];
        }
#pragma unroll
        for (int kk = 0; kk < BK; ++kk) {
            float4 av0 = *(const float4*)&As[cur][kk][ty * 8];
            float4 av1 = *(const float4*)&As[cur][kk][ty * 8 + 4];
            float4 bv  = *(const float4*)&Bs[cur][kk][tx * 4];
            const float am[8] = {av0.x, av0.y, av0.z, av0.w, av1.x, av1.y, av1.z, av1.w};
            const float bn_[4] = {bv.x, bv.y, bv.z, bv.w};
#pragma unroll
            for (int i = 0; i < 8; i++)
#pragma unroll
                for (int j = 0; j < 4; j++)
                    acc[i][j] = fmaf(am[i], bn_[j], acc[i][j]);
        }
        if (kc + 1 < NCH) {
            const int nxt = cur ^ 1;
#pragma unroll
            for (int c = 0; c < 4; c++) {
                As[nxt][kqA0 * 4 + c][rowA0] = ((const float*)&nA0)[c];
                As[nxt][kqA1 * 4 + c][rowA1] = ((const float*)&nA1)[c];
                Bs[nxt][kqB * 4 + c][rowB]   = ((const float*)&nB)[c];
            }
            __syncthreads();
        }
    }

    // epilogue with bias
    float4 bv = *(const float4*)&bias[n0 + tx * 4];
#pragma unroll
    for (int i = 0; i < 8; i++) {
        float4 o;
        o.x = acc[i][0] + bv.x;
        o.y = acc[i][1] + bv.y;
        o.z = acc[i][2] + bv.z;
        o.w = acc[i][3] + bv.w;
        *(float4*)&out[(size_t)(m0 + ty * 8 + i) * Hn + n0 + tx * 4] = o;
    }
}

// ---------------------------------------------------------------------------
// Persistent scan kernel.
// grid = 128 CTAs: group g = blockIdx.x>>4 (8 batch rows), c = blockIdx.x&15
// (32 h rows). Weights for this CTA's 32 h rows (W[h, 256:1280], 1024 floats
// each) live in smem for all 1024 steps. Lane owns one (b,h): keeps hz,hy in
// registers. Per step: stage group state (8x1024 f32) global->smem, dot via
// fma.rn.f32x2, tanh + update, write 2 state floats, group barrier.
// ---------------------------------------------------------------------------
__global__ void __launch_bounds__(256, 1) cornn_scan_kernel(
    const float* __restrict__ Wg, float* out)
{
    extern __shared__ float smem[];
    float4* Wsm = (float4*)smem;                    // 32 rows * 257 float4
    float4* Ssm = (float4*)(smem + 32 * PS);        // 8 rows  * 257 float4

    const int tid  = threadIdx.x;
    const int g    = blockIdx.x >> 4;
    const int c    = blockIdx.x & 15;
    const int hbase = c * 32;
    const int bbase = g * 8;
    const int lane = tid & 31;
    const int warp = tid >> 5;
    const int bloc = lane & 7;              // local batch row 0..7
    const int hrow = warp * 4 + (lane >> 3);// local h row 0..31
    const int h  = hbase + hrow;
    const int bg = bbase + bloc;

    // ---- load weight slice into smem (once) ----
    {
        const float4* W4 = (const float4*)Wg;
#pragma unroll 4
        for (int j = 0; j < 32; ++j) {
            // row j, float4 col tid: W[hbase+j][256 + 4*tid ...]
            Wsm[j * PS4 + tid] = W4[(size_t)(hbase + j) * (WROW / 4) + (In / 4) + tid];
        }
    }
    __syncthreads();

    // shared-window byte addresses for inline PTX
    unsigned s_waddr = (unsigned)__cvta_generic_to_shared(Wsm + hrow * PS4);
    unsigned s_saddr = (unsigned)__cvta_generic_to_shared(Ssm + bloc * PS4);

    float hz = 0.0f, hy = 0.0f;
    const size_t obase = (size_t)bg * Tn * Hn + h;   // out[bg][t][h] = obase + t*Hn
    volatile unsigned int* barp = &g_bar[g];

    for (int t = 0; t < Tn; ++t) {
        // ---- stage state (buffer t&1) global -> smem ----
        const float4* Sg4 = (const float4*)&g_state[t & 1][bbase][0];
        float4 st0 = __ldcg(Sg4 + 0 * 256 + tid);
        float4 st1 = __ldcg(Sg4 + 1 * 256 + tid);
        float4 st2 = __ldcg(Sg4 + 2 * 256 + tid);
        float4 st3 = __ldcg(Sg4 + 3 * 256 + tid);
        float4 st4 = __ldcg(Sg4 + 4 * 256 + tid);
        float4 st5 = __ldcg(Sg4 + 5 * 256 + tid);
        float4 st6 = __ldcg(Sg4 + 6 * 256 + tid);
        float4 st7 = __ldcg(Sg4 + 7 * 256 + tid);
        float xsv = out[obase + (size_t)t * Hn];   // xs[b][t][h] (written by GEMM)
        Ssm[0 * PS4 + tid] = st0;
        Ssm[1 * PS4 + tid] = st1;
        Ssm[2 * PS4 + tid] = st2;
        Ssm[3 * PS4 + tid] = st3;
        Ssm[4 * PS4 + tid] = st4;
        Ssm[5 * PS4 + tid] = st5;
        Ssm[6 * PS4 + tid] = st6;
        Ssm[7 * PS4 + tid] = st7;
        __syncthreads();

        // ---- dot product: pre = xs + sum_k s[b][k] * W[h][256+k], k<1024 ----
        unsigned long long a01 = 0ull, a23 = 0ull;   // packed f32x2 accumulators
#pragma unroll 8
        for (int kq = 0; kq < 256; ++kq) {
            unsigned long long s01, s23, w01, w23;
            asm volatile("ld.shared.v2.u64 {%0,%1},[%2];"
                         : "=l"(s01), "=l"(s23) : "r"(s_saddr + kq * 16));
            asm volatile("ld.shared.v2.u64 {%0,%1},[%2];"
                         : "=l"(w01), "=l"(w23) : "r"(s_waddr + kq * 16));
            asm("fma.rn.f32x2 %0,%1,%2,%0;" : "+l"(a01) : "l"(s01), "l"(w01));
            asm("fma.rn.f32x2 %0,%1,%2,%0;" : "+l"(a23) : "l"(s23), "l"(w23));
        }
        float a0lo, a0hi, a1lo, a1hi;
        asm("mov.b64 {%0,%1},%2;" : "=f"(a0lo), "=f"(a0hi) : "l"(a01));
        asm("mov.b64 {%0,%1},%2;" : "=f"(a1lo), "=f"(a1hi) : "l"(a23));
        float pre = xsv + ((a0lo + a0hi) + (a1lo + a1hi));

        // ---- state update (lane-owned) ----
        float th = tanhf(pre);
        hz = hz + DT_C * (th - GAMMA_C * hy - EPS_C * hz);
        hy = hy + DT_C * hz;

        // outs[b][t][h] = new hy (overwrites the consumed xs slot)
        out[obase + (size_t)t * Hn] = hy;

        // publish new state into buffer (t+1)&1
        float* Sw = &g_state[(t + 1) & 1][bg][0];
        Sw[h]      = hz;
        Sw[Hn + h] = hy;

        // ---- group barrier (monotonic counter) ----
        __syncthreads();
        if (tid == 0) {
            __threadfence();
            atomicAdd((unsigned int*)barp, 1u);
            const unsigned target = (unsigned)(GC * (t + 1));
            unsigned v;
            do {
                asm volatile("ld.acquire.gpu.global.u32 %0,[%1];"
                             : "=r"(v) : "l"((const unsigned int*)barp));
            } while (v < target);
        }
        __syncthreads();
    }

    // h_out (1, B, H) appended after outs
    out[(size_t)Bn * Tn * Hn + (size_t)bg * Hn + h] = hy;
}

// ---------------------------------------------------------------------------
extern "C" void kernel_launch(void* const* d_in, const int* in_sizes, int n_in,
                              void* d_out, int out_size)
{
    const float* x    = (const float*)d_in[0];  // (B, T, I)
    const float* W    = (const float*)d_in[1];  // (H, I + 2H)
    const float* bias = (const float*)d_in[2];  // (H,)
    float* out = (float*)d_out;                 // outs (B,T,H) then h_out (1,B,H)

    const int scan_smem = (32 + 8) * PS * 4;    // 164480 bytes
    cudaFuncSetAttribute(cornn_scan_kernel,
                         cudaFuncAttributeMaxDynamicSharedMemorySize, scan_smem);

    cornn_init_kernel<<<(Bn * KS + 255) / 256, 256>>>();
    cornn_gemm_kernel<<<dim3((Bn * Tn) / 128, Hn / 64), 256>>>(x, W, bias, out);
    cornn_scan_kernel<<<NG * GC, 256, scan_smem>>>(W, out);
}

// round 3
// speedup vs baseline: 1.8304x; 1.8304x over previous
#include <cuda_runtime.h>
#include <cstdint>

#define DT_C    0.054f
#define GAMMA_C 4.9f
#define EPS_C   4.8f

constexpr int Bn = 64, Tn = 1024, In = 256, Hn = 512;
constexpr int WROW = In + 2 * Hn;     // 1280 floats per W row
constexpr int KS   = 2 * Hn;          // 1024 state dim [hz|hy]
constexpr int NG   = 8;               // batch groups
constexpr int GC   = 16;              // CTAs per group (each owns 32 h)
constexpr int PS   = 1028;            // smem row pitch (floats)
constexpr int PS4  = PS / 4;          // 257 float4

// Scratch: double-buffered state + group barrier counters.
__device__ float g_state[2][Bn][KS];
__device__ unsigned int g_bar[NG];

// ---------------------------------------------------------------------------
__global__ void cornn_init_kernel() {
    int i = blockIdx.x * blockDim.x + threadIdx.x;
    float* s0 = &g_state[0][0][0];
    if (i < Bn * KS) s0[i] = 0.0f;
    if (i < NG) g_bar[i] = 0u;
}

// ---------------------------------------------------------------------------
// GEMM: out[m, h] = sum_i X[m, i] * W[h, i] + bias[h]
// ---------------------------------------------------------------------------
__global__ void __launch_bounds__(256) cornn_gemm_kernel(
    const float* __restrict__ X, const float* __restrict__ Wg,
    const float* __restrict__ bias, float* __restrict__ out)
{
    constexpr int BM = 128, BN = 64, BK = 16, NCH = In / BK;
    __shared__ float As[2][BK][BM + 4];
    __shared__ float Bs[2][BK][BN + 4];

    const int tid = threadIdx.x;
    const int m0 = blockIdx.x * BM;
    const int n0 = blockIdx.y * BN;
    const int tx = tid & 15;
    const int ty = tid >> 4;

    const int rowA0 = tid >> 2,         kqA0 = tid & 3;
    const int rowA1 = (tid + 256) >> 2, kqA1 = tid & 3;
    const int rowB = tid >> 2, kqB = tid & 3;

    const float4* X4 = (const float4*)X;
    const float4* W4 = (const float4*)Wg;

    float acc[8][4];
#pragma unroll
    for (int i = 0; i < 8; i++)
#pragma unroll
        for (int j = 0; j < 4; j++) acc[i][j] = 0.0f;

    float4 a0 = X4[(size_t)(m0 + rowA0) * 64 + kqA0];
    float4 a1 = X4[(size_t)(m0 + rowA1) * 64 + kqA1];
    float4 bb = W4[(size_t)(n0 + rowB) * 320 + kqB];
#pragma unroll
    for (int cc = 0; cc < 4; cc++) {
        As[0][kqA0 * 4 + cc][rowA0] = ((const float*)&a0)[cc];
        As[0][kqA1 * 4 + cc][rowA1] = ((const float*)&a1)[cc];
        Bs[0][kqB * 4 + cc][rowB]   = ((const float*)&bb)[cc];
    }
    __syncthreads();

    for (int kc = 0; kc < NCH; ++kc) {
        const int cur = kc & 1;
        float4 nA0, nA1, nB;
        if (kc + 1 < NCH) {
            nA0 = X4[(size_t)(m0 + rowA0) * 64 + (kc + 1) * 4 + kqA0];
            nA1 = X4[(size_t)(m0 + rowA1) * 64 + (kc + 1) * 4 + kqA1];
            nB  = W4[(size_t)(n0 + rowB) * 320 + (kc + 1) * 4 + kqB];
        }
#pragma unroll
        for (int kk = 0; kk < BK; ++kk) {
            float4 av0 = *(const float4*)&As[cur][kk][ty * 8];
            float4 av1 = *(const float4*)&As[cur][kk][ty * 8 + 4];
            float4 bv  = *(const float4*)&Bs[cur][kk][tx * 4];
            const float am[8] = {av0.x, av0.y, av0.z, av0.w, av1.x, av1.y, av1.z, av1.w};
            const float bn_[4] = {bv.x, bv.y, bv.z, bv.w};
#pragma unroll
            for (int i = 0; i < 8; i++)
#pragma unroll
                for (int j = 0; j < 4; j++)
                    acc[i][j] = fmaf(am[i], bn_[j], acc[i][j]);
        }
        if (kc + 1 < NCH) {
            const int nxt = cur ^ 1;
#pragma unroll
            for (int cc = 0; cc < 4; cc++) {
                As[nxt][kqA0 * 4 + cc][rowA0] = ((const float*)&nA0)[cc];
                As[nxt][kqA1 * 4 + cc][rowA1] = ((const float*)&nA1)[cc];
                Bs[nxt][kqB * 4 + cc][rowB]   = ((const float*)&nB)[cc];
            }
            __syncthreads();
        }
    }

    float4 bv = *(const float4*)&bias[n0 + tx * 4];
#pragma unroll
    for (int i = 0; i < 8; i++) {
        float4 o;
        o.x = acc[i][0] + bv.x;
        o.y = acc[i][1] + bv.y;
        o.z = acc[i][2] + bv.z;
        o.w = acc[i][3] + bv.w;
        *(float4*)&out[(size_t)(m0 + ty * 8 + i) * Hn + n0 + tx * 4] = o;
    }
}

// ---------------------------------------------------------------------------
// Persistent scan: 128 CTAs, 8 groups x 16 CTAs. CTA holds 32 W rows in smem.
// Thread = (tile=tid>>4, kp=tid&15): computes 4b x 4h partial dots over a
// 16-way-interleaved k split (quad index = kp + 16*i). Reduction via pitch-17
// smem buffer aliased with the state staging region. Final output (b,h) is
// owned by thread tid: b = tid>>5, h = tid&31.
// ---------------------------------------------------------------------------
__global__ void __launch_bounds__(256, 1) cornn_scan_kernel(
    const float* __restrict__ Wg, float* out)
{
    extern __shared__ float smem[];
    float*  Wsm  = smem;                 // 32 rows * PS floats
    float*  Ssm  = smem + 32 * PS;       // 8 rows * PS floats (aliased: red)
    float*  red  = Ssm;                  // 256 * 17 floats
    float4* Wsm4 = (float4*)Wsm;
    float4* Ssm4 = (float4*)Ssm;

    const int tid  = threadIdx.x;
    const int g    = blockIdx.x >> 4;
    const int c    = blockIdx.x & 15;
    const int hbase = c * 32;
    const int bbase = g * 8;

    const int tile = tid >> 4;          // 0..15
    const int kp   = tid & 15;          // k-part 0..15
    const int bt   = tile & 1;          // b-tile: rows bt*4..bt*4+3
    const int ht   = tile >> 1;         // h-tile: rows ht*4..ht*4+3

    // ---- resident weight slice (once) ----
    {
        const float4* W4 = (const float4*)Wg;
#pragma unroll 4
        for (int j = 0; j < 32; ++j)
            Wsm4[j * PS4 + tid] = W4[(size_t)(hbase + j) * (WROW / 4) + (In / 4) + tid];
    }
    __syncthreads();

    const unsigned s_sbase =
        (unsigned)__cvta_generic_to_shared(Ssm + bt * 4 * PS) + kp * 16;
    const unsigned s_wbase =
        (unsigned)__cvta_generic_to_shared(Wsm + ht * 4 * PS) + kp * 16;

    // final-output ownership
    const int bfin = bbase + (tid >> 5);
    const int hfin = hbase + (tid & 31);
    float hz = 0.0f, hy = 0.0f;
    const size_t obase = (size_t)bfin * Tn * Hn + hfin;
    volatile unsigned int* barp = &g_bar[g];

    for (int t = 0; t < Tn; ++t) {
        // prefetch xs for this thread's final output
        float xsv = out[obase + (size_t)t * Hn];

        // ---- stage state slab (8 rows x 1024) L2 -> smem ----
        const float4* Sg4 = (const float4*)&g_state[t & 1][bbase][0];
        float4 st[8];
#pragma unroll
        for (int r = 0; r < 8; ++r) st[r] = __ldcg(Sg4 + r * 256 + tid);
#pragma unroll
        for (int r = 0; r < 8; ++r) Ssm4[r * PS4 + tid] = st[r];
        __syncthreads();

        // ---- 4x4 packed-f32x2 dot, interleaved k-split ----
        unsigned long long acc[4][4];
#pragma unroll
        for (int i = 0; i < 4; i++)
#pragma unroll
            for (int j = 0; j < 4; j++) acc[i][j] = 0ull;

        unsigned sa = s_sbase, wa = s_wbase;
#pragma unroll 4
        for (int q = 0; q < 16; ++q) {
            unsigned long long s01[4], s23[4], w01[4], w23[4];
#pragma unroll
            for (int i = 0; i < 4; i++)
                asm volatile("ld.shared.v2.u64 {%0,%1},[%2];"
                             : "=l"(s01[i]), "=l"(s23[i])
                             : "r"(sa + i * (PS * 4)));
#pragma unroll
            for (int j = 0; j < 4; j++)
                asm volatile("ld.shared.v2.u64 {%0,%1},[%2];"
                             : "=l"(w01[j]), "=l"(w23[j])
                             : "r"(wa + j * (PS * 4)));
#pragma unroll
            for (int i = 0; i < 4; i++)
#pragma unroll
                for (int j = 0; j < 4; j++) {
                    asm("fma.rn.f32x2 %0,%1,%2,%0;"
                        : "+l"(acc[i][j]) : "l"(s01[i]), "l"(w01[j]));
                    asm("fma.rn.f32x2 %0,%1,%2,%0;"
                        : "+l"(acc[i][j]) : "l"(s23[i]), "l"(w23[j]));
                }
            sa += 256;  // next quad for this kp: +64 floats
            wa += 256;
        }
        __syncthreads();   // everyone done reading Ssm (red aliases it)

        // ---- write 16 partials to red[o*17 + kp] ----
#pragma unroll
        for (int i = 0; i < 4; i++)
#pragma unroll
            for (int j = 0; j < 4; j++) {
                float lo, hi;
                asm("mov.b64 {%0,%1},%2;" : "=f"(lo), "=f"(hi) : "l"(acc[i][j]));
                int o = (bt * 4 + i) * 32 + ht * 4 + j;
                red[o * 17 + kp] = lo + hi;
            }
        __syncthreads();

        // ---- final reduction: thread tid owns output tid ----
        float s = 0.0f;
        {
            const float* rp = red + tid * 17;
            float p0 = 0.f, p1 = 0.f, p2 = 0.f, p3 = 0.f;
#pragma unroll
            for (int k = 0; k < 16; k += 4) {
                p0 += rp[k + 0];
                p1 += rp[k + 1];
                p2 += rp[k + 2];
                p3 += rp[k + 3];
            }
            s = (p0 + p1) + (p2 + p3);
        }

        float pre = xsv + s;
        float th = tanhf(pre);
        hz = hz + DT_C * (th - GAMMA_C * hy - EPS_C * hz);
        hy = hy + DT_C * hz;

        out[obase + (size_t)t * Hn] = hy;

        float* Sw = &g_state[(t + 1) & 1][bfin][0];
        Sw[hfin]      = hz;
        Sw[Hn + hfin] = hy;

        // ---- group barrier ----
        __syncthreads();
        if (tid == 0) {
            __threadfence();
            atomicAdd((unsigned int*)barp, 1u);
            const unsigned target = (unsigned)(GC * (t + 1));
            unsigned v;
            do {
                asm volatile("ld.acquire.gpu.global.u32 %0,[%1];"
                             : "=r"(v) : "l"((const unsigned int*)barp));
            } while (v < target);
        }
        __syncthreads();
    }

    // h_out (1, B, H)
    out[(size_t)Bn * Tn * Hn + (size_t)bfin * Hn + hfin] = hy;
}

// ---------------------------------------------------------------------------
extern "C" void kernel_launch(void* const* d_in, const int* in_sizes, int n_in,
                              void* d_out, int out_size)
{
    const float* x    = (const float*)d_in[0];
    const float* W    = (const float*)d_in[1];
    const float* bias = (const float*)d_in[2];
    float* out = (float*)d_out;

    const int scan_smem = (32 + 8) * PS * 4;    // 164480 bytes
    cudaFuncSetAttribute(cornn_scan_kernel,
                         cudaFuncAttributeMaxDynamicSharedMemorySize, scan_smem);

    cornn_init_kernel<<<(Bn * KS + 255) / 256, 256>>>();
    cornn_gemm_kernel<<<dim3((Bn * Tn) / 128, Hn / 64), 256>>>(x, W, bias, out);
    cornn_scan_kernel<<<NG * GC, 256, scan_smem>>>(W, out);
}